// round 15
// baseline (speedup 1.0000x reference)
#include <cuda_runtime.h>
#include <cuda_fp16.h>

// FFM layer: out[b] = sigmoid( linear(b) + 0.5*sum_k((sum_g f)^2 - sum_g f^2) )
// f[b,g,k] = sum_d dense_x[b,d]*v[d,g,k] + sum_i v[idx[b,i],g,k]
//
// Inputs: d_in[0] dense_x f32[B,13], d_in[1] sparse_x i32[B,26],
//         d_in[2] W f32[26013], d_in[3] b f32[1], d_in[4] v f32[26013,39,8]
// Output: f32 [B]
//
// R15: main = R12's 27-row fp16 gather-add (~25us, near LTS cap). Prep's cvt
// sweep was ISSUE-bound (~13us: 1 uint4/thread, ~15 instr each). Now 4 uint4
// per thread, j-strided for perfect coalescing -> ~7 instr/uint4 amortized.
// Dense matvec keeps R14's sample-per-thread layout (256 samples/block).

namespace {
constexpr int N_DENSE  = 13;
constexpr int N_SPARSE = 26;
constexpr int ONEHOT   = 1000;
constexpr int FIELDS   = 39;
constexpr int ROWF     = FIELDS * 8;                   // 312 floats per row
constexpr int ROWH4    = FIELDS;                       // 39 uint4 per fp16 row
constexpr int N_ROWS   = N_DENSE + N_SPARSE * ONEHOT;  // 26013
constexpr int TOT      = N_ROWS * ROWF;                // 8,116,056 halves
constexpr int B_MAX    = 16384;

constexpr int SPB      = 8;                            // main: warps per block
constexpr int MTHREADS = 256;

constexpr int PTHREADS   = 256;                        // prep block size
constexpr int CVT_PER_T  = 4;                          // uint4 per thread
constexpr int CVT_N      = TOT / 8;                    // 1,014,507 uint4
constexpr int CVT_CHUNK  = PTHREADS * CVT_PER_T;       // 1024 per block
constexpr int CVT_BLOCKS = (CVT_N + CVT_CHUNK - 1) / CVT_CHUNK;  // 991
constexpr int DSPB       = PTHREADS;                   // dense samples/block
}

__device__ __align__(16) __half g_vh[TOT];             // 16.2 MB fp16 table
__device__ __align__(16) __half g_df[B_MAX * ROWF];    // 10.2 MB dense_f rows

__device__ __forceinline__ __half2 u2h2(unsigned u) {
    __half2 h; *reinterpret_cast<unsigned*>(&h) = u; return h;
}
__device__ __forceinline__ uint4 pack8(const float* f) {
    __half2 h0 = __floats2half2_rn(f[0], f[1]);
    __half2 h1 = __floats2half2_rn(f[2], f[3]);
    __half2 h2 = __floats2half2_rn(f[4], f[5]);
    __half2 h3 = __floats2half2_rn(f[6], f[7]);
    uint4 o;
    o.x = *reinterpret_cast<unsigned*>(&h0);
    o.y = *reinterpret_cast<unsigned*>(&h1);
    o.z = *reinterpret_cast<unsigned*>(&h2);
    o.w = *reinterpret_cast<unsigned*>(&h3);
    return o;
}

// ---------------------------------------------------------------- prep -----
// Blocks [0, CVT_BLOCKS): convert v fp32 -> fp16 table, 4 uint4/thread.
// Blocks [CVT_BLOCKS, ..): dense_f matvec, one sample per thread.
__global__ void __launch_bounds__(PTHREADS) prep_kernel(
    const float4* __restrict__ v4,
    const float*  __restrict__ dense_x,
    int B)
{
    const int tid = threadIdx.x;

    if (blockIdx.x < CVT_BLOCKS) {
        const int base = blockIdx.x * CVT_CHUNK + tid;   // j-strided
        uint4* outp = reinterpret_cast<uint4*>(g_vh);
        #pragma unroll
        for (int j = 0; j < CVT_PER_T; ++j) {
            int i = base + j * PTHREADS;
            if (i < CVT_N) {
                float4 a = __ldg(v4 + 2 * i);
                float4 b = __ldg(v4 + 2 * i + 1);
                float fa[8] = {a.x, a.y, a.z, a.w, b.x, b.y, b.z, b.w};
                outp[i] = pack8(fa);
            }
        }
        return;
    }

    // ---- dense_f: thread = sample ----
    __shared__ float4 s_v[N_DENSE * ROWF / 4];         // v[:13], 16224 B
    __shared__ float  s_x[DSPB * N_DENSE];             // 256 samples' dense_x

    const int base = (blockIdx.x - CVT_BLOCKS) * DSPB;
    const int b    = base + tid;

    #pragma unroll
    for (int j = tid; j < N_DENSE * ROWF / 4; j += PTHREADS)
        s_v[j] = __ldg(v4 + j);
    for (int j = tid; j < DSPB * N_DENSE; j += PTHREADS) {
        int bb = base + j / N_DENSE;
        s_x[j] = (bb < B) ? dense_x[(size_t)bb * N_DENSE + (j % N_DENSE)] : 0.0f;
    }
    __syncthreads();
    if (b >= B) return;

    float x[N_DENSE];
    #pragma unroll
    for (int d = 0; d < N_DENSE; ++d)
        x[d] = s_x[tid * N_DENSE + d];   // 13 coprime 32: conflict-free

    uint4* out4 = reinterpret_cast<uint4*>(g_df) + (size_t)b * ROWH4;
    const float4* sv = s_v;

    #pragma unroll 1
    for (int g = 0; g < FIELDS; ++g) {
        float acc[8] = {0,0,0,0,0,0,0,0};
        #pragma unroll
        for (int d = 0; d < N_DENSE; ++d) {
            // uniform broadcast LDS.128 (all lanes same address)
            float4 t0 = sv[(d * FIELDS + g) * 2];
            float4 t1 = sv[(d * FIELDS + g) * 2 + 1];
            acc[0] = fmaf(x[d], t0.x, acc[0]);
            acc[1] = fmaf(x[d], t0.y, acc[1]);
            acc[2] = fmaf(x[d], t0.z, acc[2]);
            acc[3] = fmaf(x[d], t0.w, acc[3]);
            acc[4] = fmaf(x[d], t1.x, acc[4]);
            acc[5] = fmaf(x[d], t1.y, acc[5]);
            acc[6] = fmaf(x[d], t1.z, acc[6]);
            acc[7] = fmaf(x[d], t1.w, acc[7]);
        }
        out4[g] = pack8(acc);
    }
}

// ---------------------------------------------------------------- main -----
__global__ __launch_bounds__(MTHREADS) void ffm_kernel(
    const float* __restrict__ dense_x,
    const int*   __restrict__ sparse_x,
    const float* __restrict__ W,
    const float* __restrict__ bias,
    float*       __restrict__ out,
    int B)
{
    const int tid  = threadIdx.x;
    const int lane = tid & 31;
    const int b    = blockIdx.x * SPB + (tid >> 5);
    const bool valid = (b < B);
    const bool hasB  = (lane < FIELDS - 32);           // lane < 7

    float dxr  = (valid && lane < N_DENSE) ? dense_x[b * N_DENSE + lane] : 0.0f;
    int   idxr = (valid && lane < N_SPARSE)
               ? (N_DENSE + lane * ONEHOT + sparse_x[b * N_SPARSE + lane])
               : N_DENSE;

    // Two alternating half2 accumulation chains per field.
    __half2 cA[2][4], cB[2][4];
    #pragma unroll
    for (int c = 0; c < 2; ++c)
        #pragma unroll
        for (int m = 0; m < 4; ++m) {
            cA[c][m] = __floats2half2_rn(0.0f, 0.0f);
            cB[c][m] = __floats2half2_rn(0.0f, 0.0f);
        }

    // Row 0: precomputed dense_f (same layout as a gather row).
    {
        const uint4* dr = reinterpret_cast<const uint4*>(g_df)
                        + (size_t)(valid ? b : 0) * ROWH4;
        uint4 hA = __ldg(dr + lane);
        cA[0][0] = u2h2(hA.x); cA[0][1] = u2h2(hA.y);
        cA[0][2] = u2h2(hA.z); cA[0][3] = u2h2(hA.w);
        if (hasB) {
            uint4 hB = __ldg(dr + 32 + lane);
            cB[0][0] = u2h2(hB.x); cB[0][1] = u2h2(hB.y);
            cB[0][2] = u2h2(hB.z); cB[0][3] = u2h2(hB.w);
        }
    }

    // Rows 1..26: sparse gathers.
    const uint4* vh4 = reinterpret_cast<const uint4*>(g_vh);
    #pragma unroll
    for (int i = 0; i < N_SPARSE; ++i) {
        const int r = __shfl_sync(0xffffffffu, idxr, i);
        const uint4* rp = vh4 + (size_t)r * ROWH4;
        const int c = i & 1;
        uint4 hA = __ldg(rp + lane);
        cA[c][0] = __hadd2(cA[c][0], u2h2(hA.x));
        cA[c][1] = __hadd2(cA[c][1], u2h2(hA.y));
        cA[c][2] = __hadd2(cA[c][2], u2h2(hA.z));
        cA[c][3] = __hadd2(cA[c][3], u2h2(hA.w));
        if (hasB) {
            uint4 hB = __ldg(rp + 32 + lane);
            cB[c][0] = __hadd2(cB[c][0], u2h2(hB.x));
            cB[c][1] = __hadd2(cB[c][1], u2h2(hB.y));
            cB[c][2] = __hadd2(cB[c][2], u2h2(hB.z));
            cB[c][3] = __hadd2(cB[c][3], u2h2(hB.w));
        }
    }

    // Merge chains to fp32 per-field vectors.
    float fA[8], fB[8];
    #pragma unroll
    for (int m = 0; m < 4; ++m) {
        float2 a0 = __half22float2(cA[0][m]);
        float2 a1 = __half22float2(cA[1][m]);
        fA[2 * m]     = a0.x + a1.x;
        fA[2 * m + 1] = a0.y + a1.y;
        float2 b0 = __half22float2(cB[0][m]);
        float2 b1 = __half22float2(cB[1][m]);
        fB[2 * m]     = b0.x + b1.x;
        fB[2 * m + 1] = b0.y + b1.y;
    }

    // Epilogue (fp32).
    float s[8], q = 0.0f;
    #pragma unroll
    for (int k = 0; k < 8; ++k) {
        s[k] = fA[k] + fB[k];
        q = fmaf(fA[k], fA[k], q);
        q = fmaf(fB[k], fB[k], q);
    }

    float lin = 0.0f;
    if (lane < N_SPARSE) lin = __ldg(W + idxr);
    if (lane < N_DENSE)  lin = fmaf(dxr, __ldg(W + lane), lin);

    #pragma unroll
    for (int m = 16; m >= 1; m >>= 1) {
        q   += __shfl_xor_sync(0xffffffffu, q, m);
        lin += __shfl_xor_sync(0xffffffffu, lin, m);
    }
    #pragma unroll
    for (int k = 0; k < 8; ++k)
        #pragma unroll
        for (int m = 16; m >= 1; m >>= 1)
            s[k] += __shfl_xor_sync(0xffffffffu, s[k], m);

    float ss = 0.0f;
    #pragma unroll
    for (int k = 0; k < 8; ++k) ss = fmaf(s[k], s[k], ss);

    if (lane == 0 && valid) {
        float z = lin + 0.5f * (ss - q) + __ldg(bias);
        out[b] = 1.0f / (1.0f + expf(-z));
    }
}

extern "C" void kernel_launch(void* const* d_in, const int* in_sizes, int n_in,
                              void* d_out, int out_size)
{
    const float* dense_x  = (const float*)d_in[0];
    const int*   sparse_x = (const int*)  d_in[1];
    const float* W        = (const float*)d_in[2];
    const float* bias     = (const float*)d_in[3];
    const float* v        = (const float*)d_in[4];
    float*       out      = (float*)d_out;

    const int B = in_sizes[0] / N_DENSE;
    const int dense_blocks = (B + DSPB - 1) / DSPB;

    prep_kernel<<<CVT_BLOCKS + dense_blocks, PTHREADS>>>(
        reinterpret_cast<const float4*>(v), dense_x, B);

    ffm_kernel<<<(B + SPB - 1) / SPB, MTHREADS>>>(
        dense_x, sparse_x, W, bias, out, B);
}

// round 16
// speedup vs baseline: 1.4604x; 1.4604x over previous
#include <cuda_runtime.h>
#include <cuda_fp16.h>

// FFM layer: out[b] = sigmoid( linear(b) + 0.5*sum_k((sum_g f)^2 - sum_g f^2) )
// f[b,g,k] = sum_d dense_x[b,d]*v[d,g,k] + sum_i v[idx[b,i],g,k]
//
// Inputs: d_in[0] dense_x f32[B,13], d_in[1] sparse_x i32[B,26],
//         d_in[2] W f32[26013], d_in[3] b f32[1], d_in[4] v f32[26013,39,8]
// Output: f32 [B]
//
// R16: TWO kernels. (1) cvt: v fp32 -> fp16 table, rows PADDED to 40 uint4
// (640B = exactly 5 aligned 128B lines; slot 39 = zeros). (2) main: the
// dense part is NOT precomputed anymore (g_df and its DRAM cycling killed);
// table rows 0..12 ARE v[:13] in fp16 -> staged in 8.3KB smem per block and
// accumulated per warp with 13 HFMA2 steps into the same half2 chains as
// the 26 sparse gathers.

namespace {
constexpr int N_DENSE  = 13;
constexpr int N_SPARSE = 26;
constexpr int ONEHOT   = 1000;
constexpr int FIELDS   = 39;
constexpr int ROWP     = 40;                           // padded uint4 per row
constexpr int N_ROWS   = N_DENSE + N_SPARSE * ONEHOT;  // 26013
constexpr int TOTP     = N_ROWS * ROWP * 8;            // padded halves
constexpr int CVT_OUT  = N_ROWS * ROWP;                // 1,040,520 uint4
constexpr int SPB      = 8;                            // main: warps per block
constexpr int MTHREADS = 256;
constexpr int CTHREADS = 256;
}

__device__ __align__(16) __half g_vh[TOTP];            // 16.65 MB fp16 table

__device__ __forceinline__ __half2 u2h2(unsigned u) {
    __half2 h; *reinterpret_cast<unsigned*>(&h) = u; return h;
}

// ----------------------------------------------------------------- cvt -----
// One output uint4 per thread. Output row r slot j: j<39 -> convert 8 floats
// from v[r*312 + 8j ..]; j==39 -> zeros (padding).
__global__ void __launch_bounds__(CTHREADS) cvt_kernel(
    const float4* __restrict__ v4)
{
    unsigned i = blockIdx.x * CTHREADS + threadIdx.x;
    if (i >= CVT_OUT) return;
    unsigned r = i / ROWP;
    unsigned j = i - r * ROWP;
    uint4 o = {0u, 0u, 0u, 0u};
    if (j < (unsigned)FIELDS) {
        const float4 a = __ldg(v4 + (size_t)r * 78 + 2 * j);
        const float4 b = __ldg(v4 + (size_t)r * 78 + 2 * j + 1);
        __half2 h0 = __floats2half2_rn(a.x, a.y);
        __half2 h1 = __floats2half2_rn(a.z, a.w);
        __half2 h2 = __floats2half2_rn(b.x, b.y);
        __half2 h3 = __floats2half2_rn(b.z, b.w);
        o.x = *reinterpret_cast<unsigned*>(&h0);
        o.y = *reinterpret_cast<unsigned*>(&h1);
        o.z = *reinterpret_cast<unsigned*>(&h2);
        o.w = *reinterpret_cast<unsigned*>(&h3);
    }
    reinterpret_cast<uint4*>(g_vh)[i] = o;
}

// ---------------------------------------------------------------- main -----
__global__ __launch_bounds__(MTHREADS) void ffm_kernel(
    const float* __restrict__ dense_x,
    const int*   __restrict__ sparse_x,
    const float* __restrict__ W,
    const float* __restrict__ bias,
    float*       __restrict__ out,
    int B)
{
    __shared__ uint4 s_vd[N_DENSE * ROWP];             // fp16 v[:13], 8320 B

    const int tid  = threadIdx.x;
    const int lane = tid & 31;
    const int b    = blockIdx.x * SPB + (tid >> 5);
    const bool valid = (b < B);
    const bool hasB  = (lane < 8);                     // slots 32..39 (39=pad)

    const uint4* vh4 = reinterpret_cast<const uint4*>(g_vh);

    // Stage the 13 dense rows of the fp16 table (table rows 0..12).
    #pragma unroll
    for (int j = tid; j < N_DENSE * ROWP; j += MTHREADS)
        s_vd[j] = __ldg(vh4 + j);
    __syncthreads();

    float dxr  = (valid && lane < N_DENSE) ? dense_x[b * N_DENSE + lane] : 0.0f;
    int   idxr = (valid && lane < N_SPARSE)
               ? (N_DENSE + lane * ONEHOT + sparse_x[b * N_SPARSE + lane])
               : N_DENSE;

    // Two alternating half2 accumulation chains per slot.
    __half2 cA[2][4], cB[2][4];
    #pragma unroll
    for (int c = 0; c < 2; ++c)
        #pragma unroll
        for (int m = 0; m < 4; ++m) {
            cA[c][m] = __floats2half2_rn(0.0f, 0.0f);
            cB[c][m] = __floats2half2_rn(0.0f, 0.0f);
        }

    // Dense contribution: 13 HFMA2 row-accumulates from smem.
    #pragma unroll
    for (int d = 0; d < N_DENSE; ++d) {
        const float  xf = __shfl_sync(0xffffffffu, dxr, d);
        const __half2 xh = __float2half2_rn(xf);
        const int c = d & 1;
        uint4 a = s_vd[d * ROWP + lane];
        cA[c][0] = __hfma2(xh, u2h2(a.x), cA[c][0]);
        cA[c][1] = __hfma2(xh, u2h2(a.y), cA[c][1]);
        cA[c][2] = __hfma2(xh, u2h2(a.z), cA[c][2]);
        cA[c][3] = __hfma2(xh, u2h2(a.w), cA[c][3]);
        if (hasB) {
            uint4 q = s_vd[d * ROWP + 32 + lane];
            cB[c][0] = __hfma2(xh, u2h2(q.x), cB[c][0]);
            cB[c][1] = __hfma2(xh, u2h2(q.y), cB[c][1]);
            cB[c][2] = __hfma2(xh, u2h2(q.z), cB[c][2]);
            cB[c][3] = __hfma2(xh, u2h2(q.w), cB[c][3]);
        }
    }

    // Sparse gathers: 26 padded rows, each exactly 5 aligned 128B lines.
    #pragma unroll
    for (int i = 0; i < N_SPARSE; ++i) {
        const int r = __shfl_sync(0xffffffffu, idxr, i);
        const uint4* rp = vh4 + (size_t)r * ROWP;
        const int c = i & 1;
        uint4 hA = __ldg(rp + lane);
        cA[c][0] = __hadd2(cA[c][0], u2h2(hA.x));
        cA[c][1] = __hadd2(cA[c][1], u2h2(hA.y));
        cA[c][2] = __hadd2(cA[c][2], u2h2(hA.z));
        cA[c][3] = __hadd2(cA[c][3], u2h2(hA.w));
        if (hasB) {
            uint4 hB = __ldg(rp + 32 + lane);
            cB[c][0] = __hadd2(cB[c][0], u2h2(hB.x));
            cB[c][1] = __hadd2(cB[c][1], u2h2(hB.y));
            cB[c][2] = __hadd2(cB[c][2], u2h2(hB.z));
            cB[c][3] = __hadd2(cB[c][3], u2h2(hB.w));
        }
    }

    // Merge chains to fp32 per-slot vectors.
    float fA[8], fB[8];
    #pragma unroll
    for (int m = 0; m < 4; ++m) {
        float2 a0 = __half22float2(cA[0][m]);
        float2 a1 = __half22float2(cA[1][m]);
        fA[2 * m]     = a0.x + a1.x;
        fA[2 * m + 1] = a0.y + a1.y;
        float2 b0 = __half22float2(cB[0][m]);
        float2 b1 = __half22float2(cB[1][m]);
        fB[2 * m]     = b0.x + b1.x;
        fB[2 * m + 1] = b0.y + b1.y;
    }

    // Epilogue (fp32). Pad slot is zero: contributes nothing to s or q.
    float s[8], q = 0.0f;
    #pragma unroll
    for (int k = 0; k < 8; ++k) {
        s[k] = fA[k] + fB[k];
        q = fmaf(fA[k], fA[k], q);
        q = fmaf(fB[k], fB[k], q);
    }

    float lin = 0.0f;
    if (lane < N_SPARSE) lin = __ldg(W + idxr);
    if (lane < N_DENSE)  lin = fmaf(dxr, __ldg(W + lane), lin);

    #pragma unroll
    for (int m = 16; m >= 1; m >>= 1) {
        q   += __shfl_xor_sync(0xffffffffu, q, m);
        lin += __shfl_xor_sync(0xffffffffu, lin, m);
    }
    #pragma unroll
    for (int k = 0; k < 8; ++k)
        #pragma unroll
        for (int m = 16; m >= 1; m >>= 1)
            s[k] += __shfl_xor_sync(0xffffffffu, s[k], m);

    float ss = 0.0f;
    #pragma unroll
    for (int k = 0; k < 8; ++k) ss = fmaf(s[k], s[k], ss);

    if (lane == 0 && valid) {
        float z = lin + 0.5f * (ss - q) + __ldg(bias);
        out[b] = 1.0f / (1.0f + expf(-z));
    }
}

extern "C" void kernel_launch(void* const* d_in, const int* in_sizes, int n_in,
                              void* d_out, int out_size)
{
    const float* dense_x  = (const float*)d_in[0];
    const int*   sparse_x = (const int*)  d_in[1];
    const float* W        = (const float*)d_in[2];
    const float* bias     = (const float*)d_in[3];
    const float* v        = (const float*)d_in[4];
    float*       out      = (float*)d_out;

    const int B = in_sizes[0] / N_DENSE;

    cvt_kernel<<<(CVT_OUT + CTHREADS - 1) / CTHREADS, CTHREADS>>>(
        reinterpret_cast<const float4*>(v));

    ffm_kernel<<<(B + SPB - 1) / SPB, MTHREADS>>>(
        dense_x, sparse_x, W, bias, out, B);
}

// round 17
// speedup vs baseline: 1.4710x; 1.0072x over previous
#include <cuda_runtime.h>
#include <cuda_fp16.h>

// FFM layer: out[b] = sigmoid( linear(b) + 0.5*sum_k((sum_g f)^2 - sum_g f^2) )
// f[b,g,k] = sum_d dense_x[b,d]*v[d,g,k] + sum_i v[idx[b,i],g,k]
//
// Inputs: d_in[0] dense_x f32[B,13], d_in[1] sparse_x i32[B,26],
//         d_in[2] W f32[26013], d_in[3] b f32[1], d_in[4] v f32[26013,39,8]
// Output: f32 [B]
//
// R17: cvt unchanged (fp16 table, rows padded to 40 uint4 = 5 x 128B lines).
// Main is now SMEM-FREE: the 13 dense rows are table rows 0..12 and stay
// L1-resident (every warp on the SM reads the same 8.3KB), so no staging,
// no __syncthreads, no block-granular bubbles. Per warp: prefetch the first
// two gather rows, run the dense HFMA2 section inside their latency shadow,
// then a depth-2 software-pipelined gather accumulate.

namespace {
constexpr int N_DENSE  = 13;
constexpr int N_SPARSE = 26;
constexpr int ONEHOT   = 1000;
constexpr int FIELDS   = 39;
constexpr int ROWP     = 40;                           // padded uint4 per row
constexpr int N_ROWS   = N_DENSE + N_SPARSE * ONEHOT;  // 26013
constexpr int TOTP     = N_ROWS * ROWP * 8;            // padded halves
constexpr int CVT_OUT  = N_ROWS * ROWP;                // 1,040,520 uint4
constexpr int SPB      = 8;                            // main: warps per block
constexpr int MTHREADS = 256;
constexpr int CTHREADS = 256;
}

__device__ __align__(16) __half g_vh[TOTP];            // 16.65 MB fp16 table

__device__ __forceinline__ __half2 u2h2(unsigned u) {
    __half2 h; *reinterpret_cast<unsigned*>(&h) = u; return h;
}

// ----------------------------------------------------------------- cvt -----
__global__ void __launch_bounds__(CTHREADS) cvt_kernel(
    const float4* __restrict__ v4)
{
    unsigned i = blockIdx.x * CTHREADS + threadIdx.x;
    if (i >= CVT_OUT) return;
    unsigned r = i / ROWP;
    unsigned j = i - r * ROWP;
    uint4 o = {0u, 0u, 0u, 0u};
    if (j < (unsigned)FIELDS) {
        const float4 a = __ldg(v4 + (size_t)r * 78 + 2 * j);
        const float4 b = __ldg(v4 + (size_t)r * 78 + 2 * j + 1);
        __half2 h0 = __floats2half2_rn(a.x, a.y);
        __half2 h1 = __floats2half2_rn(a.z, a.w);
        __half2 h2 = __floats2half2_rn(b.x, b.y);
        __half2 h3 = __floats2half2_rn(b.z, b.w);
        o.x = *reinterpret_cast<unsigned*>(&h0);
        o.y = *reinterpret_cast<unsigned*>(&h1);
        o.z = *reinterpret_cast<unsigned*>(&h2);
        o.w = *reinterpret_cast<unsigned*>(&h3);
    }
    reinterpret_cast<uint4*>(g_vh)[i] = o;
}

// ---------------------------------------------------------------- main -----
__global__ __launch_bounds__(MTHREADS) void ffm_kernel(
    const float* __restrict__ dense_x,
    const int*   __restrict__ sparse_x,
    const float* __restrict__ W,
    const float* __restrict__ bias,
    float*       __restrict__ out,
    int B)
{
    const int tid  = threadIdx.x;
    const int lane = tid & 31;
    const int b    = blockIdx.x * SPB + (tid >> 5);
    const bool valid = (b < B);
    const bool hasB  = (lane < 8);                     // slots 32..39 (39=pad)

    const uint4* vh4 = reinterpret_cast<const uint4*>(g_vh);

    float dxr  = (valid && lane < N_DENSE) ? dense_x[b * N_DENSE + lane] : 0.0f;
    int   idxr = (valid && lane < N_SPARSE)
               ? (N_DENSE + lane * ONEHOT + sparse_x[b * N_SPARSE + lane])
               : N_DENSE;

    // Two alternating half2 accumulation chains per slot.
    __half2 cA[2][4], cB[2][4];
    #pragma unroll
    for (int c = 0; c < 2; ++c)
        #pragma unroll
        for (int m = 0; m < 4; ++m) {
            cA[c][m] = __floats2half2_rn(0.0f, 0.0f);
            cB[c][m] = __floats2half2_rn(0.0f, 0.0f);
        }

    // ---- Prefetch gather rows 0 and 1 (fly during the dense section). ----
    uint4 pA[2], pB[2];
    #pragma unroll
    for (int j = 0; j < 2; ++j) {
        const int r = __shfl_sync(0xffffffffu, idxr, j);
        const uint4* rp = vh4 + (size_t)r * ROWP;
        pA[j] = __ldg(rp + lane);
        pB[j] = make_uint4(0u, 0u, 0u, 0u);
        if (hasB) pB[j] = __ldg(rp + 32 + lane);
    }

    // ---- Dense contribution: table rows 0..12 are v[:13] in fp16 (L1-hot).
    #pragma unroll
    for (int d = 0; d < N_DENSE; ++d) {
        const float   xf = __shfl_sync(0xffffffffu, dxr, d);
        const __half2 xh = __float2half2_rn(xf);
        const int c = d & 1;
        const uint4* rp = vh4 + (size_t)d * ROWP;
        uint4 a = __ldg(rp + lane);
        cA[c][0] = __hfma2(xh, u2h2(a.x), cA[c][0]);
        cA[c][1] = __hfma2(xh, u2h2(a.y), cA[c][1]);
        cA[c][2] = __hfma2(xh, u2h2(a.z), cA[c][2]);
        cA[c][3] = __hfma2(xh, u2h2(a.w), cA[c][3]);
        if (hasB) {
            uint4 q = __ldg(rp + 32 + lane);
            cB[c][0] = __hfma2(xh, u2h2(q.x), cB[c][0]);
            cB[c][1] = __hfma2(xh, u2h2(q.y), cB[c][1]);
            cB[c][2] = __hfma2(xh, u2h2(q.z), cB[c][2]);
            cB[c][3] = __hfma2(xh, u2h2(q.w), cB[c][3]);
        }
    }

    // ---- Sparse gathers: depth-2 software pipeline. ----
    #pragma unroll
    for (int i = 0; i < N_SPARSE; ++i) {
        const int buf = i & 1;
        const int c   = i & 1;
        uint4 hA = pA[buf];
        uint4 hB = pB[buf];
        // Prefetch row i+2 into the buffer we just consumed.
        if (i + 2 < N_SPARSE) {
            const int r = __shfl_sync(0xffffffffu, idxr, i + 2);
            const uint4* rp = vh4 + (size_t)r * ROWP;
            pA[buf] = __ldg(rp + lane);
            if (hasB) pB[buf] = __ldg(rp + 32 + lane);
        }
        cA[c][0] = __hadd2(cA[c][0], u2h2(hA.x));
        cA[c][1] = __hadd2(cA[c][1], u2h2(hA.y));
        cA[c][2] = __hadd2(cA[c][2], u2h2(hA.z));
        cA[c][3] = __hadd2(cA[c][3], u2h2(hA.w));
        if (hasB) {
            cB[c][0] = __hadd2(cB[c][0], u2h2(hB.x));
            cB[c][1] = __hadd2(cB[c][1], u2h2(hB.y));
            cB[c][2] = __hadd2(cB[c][2], u2h2(hB.z));
            cB[c][3] = __hadd2(cB[c][3], u2h2(hB.w));
        }
    }

    // Merge chains to fp32 per-slot vectors.
    float fA[8], fB[8];
    #pragma unroll
    for (int m = 0; m < 4; ++m) {
        float2 a0 = __half22float2(cA[0][m]);
        float2 a1 = __half22float2(cA[1][m]);
        fA[2 * m]     = a0.x + a1.x;
        fA[2 * m + 1] = a0.y + a1.y;
        float2 b0 = __half22float2(cB[0][m]);
        float2 b1 = __half22float2(cB[1][m]);
        fB[2 * m]     = b0.x + b1.x;
        fB[2 * m + 1] = b0.y + b1.y;
    }

    // Epilogue (fp32). Pad slot is zero: contributes nothing to s or q.
    float s[8], q = 0.0f;
    #pragma unroll
    for (int k = 0; k < 8; ++k) {
        s[k] = fA[k] + fB[k];
        q = fmaf(fA[k], fA[k], q);
        q = fmaf(fB[k], fB[k], q);
    }

    float lin = 0.0f;
    if (lane < N_SPARSE) lin = __ldg(W + idxr);
    if (lane < N_DENSE)  lin = fmaf(dxr, __ldg(W + lane), lin);

    #pragma unroll
    for (int m = 16; m >= 1; m >>= 1) {
        q   += __shfl_xor_sync(0xffffffffu, q, m);
        lin += __shfl_xor_sync(0xffffffffu, lin, m);
    }
    #pragma unroll
    for (int k = 0; k < 8; ++k)
        #pragma unroll
        for (int m = 16; m >= 1; m >>= 1)
            s[k] += __shfl_xor_sync(0xffffffffu, s[k], m);

    float ss = 0.0f;
    #pragma unroll
    for (int k = 0; k < 8; ++k) ss = fmaf(s[k], s[k], ss);

    if (lane == 0 && valid) {
        float z = lin + 0.5f * (ss - q) + __ldg(bias);
        out[b] = 1.0f / (1.0f + expf(-z));
    }
}

extern "C" void kernel_launch(void* const* d_in, const int* in_sizes, int n_in,
                              void* d_out, int out_size)
{
    const float* dense_x  = (const float*)d_in[0];
    const int*   sparse_x = (const int*)  d_in[1];
    const float* W        = (const float*)d_in[2];
    const float* bias     = (const float*)d_in[3];
    const float* v        = (const float*)d_in[4];
    float*       out      = (float*)d_out;

    const int B = in_sizes[0] / N_DENSE;

    cvt_kernel<<<(CVT_OUT + CTHREADS - 1) / CTHREADS, CTHREADS>>>(
        reinterpret_cast<const float4*>(v));

    ffm_kernel<<<(B + SPB - 1) / SPB, MTHREADS>>>(
        dense_x, sparse_x, W, bias, out, B);
}